// round 3
// baseline (speedup 1.0000x reference)
#include <cuda_runtime.h>
#include <cstdint>

#define TS 47

// ---------------- device scratch (allocation-free) ----------------
__device__ __align__(128) float g_features[8192 * 256];
__device__ __align__(128) float g_featw1 [8192 * 512];
__device__ __align__(128) float g_embtok [6016 * 256];
__device__ __align__(128) float g_embmx  [6016 * 1536];
__device__ __align__(128) float g_mx     [128 * 1536];
__device__ __align__(128) float g_hidw2  [2 * 128 * 512];
__device__ __align__(128) float g_context[128 * 256];
__device__ __align__(128) float g_states [6016 * 512];
__device__ __align__(128) float g_fc1out [6016 * 512];

__device__ unsigned g_bar_cnt;   // returns to 0 after every barrier
__device__ unsigned g_bar_gen;   // monotonic generation counter

// ---------------- helpers ----------------
__device__ __forceinline__ float tanh_apx(float x) {
    float y;
    asm("tanh.approx.f32 %0, %1;" : "=f"(y) : "f"(x));
    return y;
}

__device__ __forceinline__ void fma2(unsigned long long& d,
                                     unsigned long long a,
                                     unsigned long long b) {
    asm("fma.rn.f32x2 %0, %1, %2, %0;" : "+l"(d) : "l"(a), "l"(b));
}

__device__ __forceinline__ unsigned ld_acq(const unsigned* p) {
    unsigned v;
    asm volatile("ld.acquire.gpu.global.u32 %0, [%1];" : "=r"(v) : "l"(p));
    return v;
}

__device__ __forceinline__ void grid_bar(int nblk) {
    __syncthreads();
    if (threadIdx.x == 0) {
        unsigned gen = ld_acq(&g_bar_gen);
        __threadfence();
        if (atomicAdd(&g_bar_cnt, 1u) == (unsigned)(nblk - 1)) {
            g_bar_cnt = 0;
            asm volatile("red.release.gpu.global.add.u32 [%0], 1;"
                         :: "l"(&g_bar_gen) : "memory");
        } else {
            while (ld_acq(&g_bar_gen) == gen) __nanosleep(64);
        }
    }
    __syncthreads();
}

// ---------------- big GEMM, packed f32x2: 128x128 tile, BK=8, 8x8 micro ----------------
// C[M,N] = act(A[M,K] @ B[K,N] + bias). M%128==0, K%8==0. N guarded.
// remap: A-row (t*128+b) stored to C-row (b*47+t).
__global__ __launch_bounds__(256, 2) void sgemm128_f2(
    const float* __restrict__ A, const float* __restrict__ B,
    const float* __restrict__ bias, float* __restrict__ C,
    int M, int N, int K, int relu, int remap)
{
    __shared__ __align__(16) float As2[8 * 256];  // duplicated (a,a) pairs
    __shared__ __align__(16) float Bs [8 * 128];

    int tid = threadIdx.x;
    int bm = blockIdx.y * 128;
    int bn = blockIdx.x * 128;
    int ar = tid >> 1;            // 0..127
    int ac = (tid & 1) * 4;       // 0 or 4
    int br = tid >> 5;            // 0..7
    int bc = (tid & 31) * 4;      // 0..124
    int tx = tid & 15, ty = tid >> 4;

    unsigned long long acc[8][4] = {};
    const float* Ap = A + (size_t)(bm + ar) * K + ac;

    for (int k0 = 0; k0 < K; k0 += 8) {
        float4 av = *(const float4*)(Ap + k0);
        *(float2*)&As2[(ac + 0) * 256 + 2 * ar] = make_float2(av.x, av.x);
        *(float2*)&As2[(ac + 1) * 256 + 2 * ar] = make_float2(av.y, av.y);
        *(float2*)&As2[(ac + 2) * 256 + 2 * ar] = make_float2(av.z, av.z);
        *(float2*)&As2[(ac + 3) * 256 + 2 * ar] = make_float2(av.w, av.w);

        int gc = bn + bc;
        const float* Bp = B + (size_t)(k0 + br) * N + gc;
        float4 bv;
        if (gc + 3 < N) {
            bv = *(const float4*)Bp;
        } else {
            bv.x = (gc + 0 < N) ? Bp[0] : 0.f;
            bv.y = (gc + 1 < N) ? Bp[1] : 0.f;
            bv.z = (gc + 2 < N) ? Bp[2] : 0.f;
            bv.w = (gc + 3 < N) ? Bp[3] : 0.f;
        }
        *(float4*)&Bs[br * 128 + bc] = bv;
        __syncthreads();

        #pragma unroll
        for (int k = 0; k < 8; k++) {
            const unsigned long long* ap = (const unsigned long long*)&As2[k * 256];
            const unsigned long long* bp = (const unsigned long long*)&Bs[k * 128];
            unsigned long long a2[8], b2[4];
            #pragma unroll
            for (int i = 0; i < 4; i++) {
                a2[i]     = ap[ty * 4 + i];
                a2[i + 4] = ap[64 + ty * 4 + i];
            }
            b2[0] = bp[tx * 2];
            b2[1] = bp[tx * 2 + 1];
            b2[2] = bp[32 + tx * 2];
            b2[3] = bp[32 + tx * 2 + 1];
            #pragma unroll
            for (int i = 0; i < 8; i++)
                #pragma unroll
                for (int j = 0; j < 4; j++)
                    fma2(acc[i][j], a2[i], b2[j]);
        }
        __syncthreads();
    }

    #pragma unroll
    for (int i = 0; i < 8; i++) {
        int grow = bm + ((i < 4) ? (ty * 4 + i) : (64 + ty * 4 + i - 4));
        size_t ro;
        if (remap) {
            int t = grow >> 7, b = grow & 127;
            ro = ((size_t)b * TS + t) * (size_t)N;
        } else {
            ro = (size_t)grow * (size_t)N;
        }
        #pragma unroll
        for (int j = 0; j < 4; j++) {
            int c = bn + ((j < 2) ? (tx * 4 + j * 2) : (64 + tx * 4 + (j - 2) * 2));
            float lo = __uint_as_float((unsigned)(acc[i][j] & 0xFFFFFFFFull));
            float hi = __uint_as_float((unsigned)(acc[i][j] >> 32));
            if (c < N) {
                float v = lo + (bias ? bias[c] : 0.f);
                if (relu) v = fmaxf(v, 0.f);
                C[ro + c] = v;
            }
            if (c + 1 < N) {
                float v = hi + (bias ? bias[c + 1] : 0.f);
                if (relu) v = fmaxf(v, 0.f);
                C[ro + c + 1] = v;
            }
        }
    }
}

// ---------------- token embedding gather ----------------
__global__ void gather_kernel(const int* __restrict__ target,
                              const float* __restrict__ emb)
{
    int row = blockIdx.x;          // t*128 + b
    int e = threadIdx.x;           // 256
    int t = row >> 7, b = row & 127;
    int tok = (t == 0) ? 1 : target[b * 48 + t];
    g_embtok[(size_t)row * 256 + e] = emb[(size_t)tok * 256 + e];
}

// ---------------- persistent step loop: 128 blocks, all 47 timesteps ----------------
__global__ __launch_bounds__(256) void step_loop_kernel(
    const float* __restrict__ W2, const float* __restrict__ V,
    const float* __restrict__ bV, const float* __restrict__ b2,
    const float* __restrict__ gru_k, const float* __restrict__ gru_b)
{
    __shared__ float sm[1664];
    const int bid = blockIdx.x;   // 0..127
    const int tid = threadIdx.x;  // 0..255
    const int nblk = 128;

    for (int t = 0; t < TS; t++) {
        // ---- Phase A: hidw2 = states[t-1] @ W2 (K-split 2, 32x32 tiles) ----
        if (t > 0) {
            float* As = sm;            // 16x32
            float* Bs = sm + 512;      // 16x32
            int z  = bid >> 6;
            int rr = bid & 63;
            int bm = (rr >> 4) * 32;
            int bn = (rr & 15) * 32;
            const float* A = g_states + (size_t)(t - 1) * 65536;
            float* C = g_hidw2 + z * 65536;
            int kbeg = z * 256;
            int arow = tid >> 3, akc = (tid & 7) * 2;
            int bkr = tid >> 4, bnc = (tid & 15) * 2;
            int tx = tid & 15, ty = tid >> 4;
            float a00 = 0.f, a01 = 0.f, a10 = 0.f, a11 = 0.f;
            for (int k0 = kbeg; k0 < kbeg + 256; k0 += 16) {
                float2 av = *(const float2*)(A + (size_t)(bm + arow) * 512 + k0 + akc);
                As[(akc + 0) * 32 + arow] = av.x;
                As[(akc + 1) * 32 + arow] = av.y;
                float2 bv = *(const float2*)(W2 + (size_t)(k0 + bkr) * 512 + bn + bnc);
                Bs[bkr * 32 + bnc + 0] = bv.x;
                Bs[bkr * 32 + bnc + 1] = bv.y;
                __syncthreads();
                #pragma unroll
                for (int k = 0; k < 16; k++) {
                    float2 a = *(const float2*)&As[k * 32 + ty * 2];
                    float2 b = *(const float2*)&Bs[k * 32 + tx * 2];
                    a00 = fmaf(a.x, b.x, a00); a01 = fmaf(a.x, b.y, a01);
                    a10 = fmaf(a.y, b.x, a10); a11 = fmaf(a.y, b.y, a11);
                }
                __syncthreads();
            }
            int r0 = bm + ty * 2, c0 = bn + tx * 2;
            C[(size_t)(r0 + 0) * 512 + c0 + 0] = a00;
            C[(size_t)(r0 + 0) * 512 + c0 + 1] = a01;
            C[(size_t)(r0 + 1) * 512 + c0 + 0] = a10;
            C[(size_t)(r0 + 1) * 512 + c0 + 1] = a11;
            grid_bar(nblk);
        }

        // ---- Phase B: Bahdanau attention, block = batch element ----
        {
            float* hw2 = sm;          // 512
            float* sV  = sm + 512;    // 512
            float* sl  = sm + 1024;   // 64
            int b = bid;
            if (t > 0) {
                hw2[tid]       = g_hidw2[b * 512 + tid]       + g_hidw2[65536 + b * 512 + tid]       + b2[tid];
                hw2[tid + 256] = g_hidw2[b * 512 + tid + 256] + g_hidw2[65536 + b * 512 + tid + 256] + b2[tid + 256];
            } else {
                hw2[tid]       = b2[tid];
                hw2[tid + 256] = b2[tid + 256];
            }
            sV[tid]       = V[tid];
            sV[tid + 256] = V[tid + 256];
            __syncthreads();

            int w = tid >> 5, lane = tid & 31;
            #pragma unroll
            for (int p = 0; p < 8; p++) {
                int l = w * 8 + p;
                const float* row = g_featw1 + ((size_t)b * 64 + l) * 512;
                float a = 0.f;
                #pragma unroll
                for (int j = 0; j < 16; j++) {
                    int u = lane + j * 32;
                    float s = tanh_apx(row[u] + hw2[u]);
                    a = fmaf(s, sV[u], a);
                }
                #pragma unroll
                for (int o = 16; o; o >>= 1) a += __shfl_xor_sync(0xffffffffu, a, o);
                if (lane == 0) sl[l] = a + bV[0];
            }
            __syncthreads();

            if (tid < 32) {
                float v0 = sl[tid], v1 = sl[tid + 32];
                float m = fmaxf(v0, v1);
                #pragma unroll
                for (int o = 16; o; o >>= 1) m = fmaxf(m, __shfl_xor_sync(0xffffffffu, m, o));
                float e0 = __expf(v0 - m), e1 = __expf(v1 - m);
                float s = e0 + e1;
                #pragma unroll
                for (int o = 16; o; o >>= 1) s += __shfl_xor_sync(0xffffffffu, s, o);
                float inv = 1.0f / s;
                sl[tid] = e0 * inv;
                sl[tid + 32] = e1 * inv;
            }
            __syncthreads();

            float c = 0.f;
            #pragma unroll 8
            for (int l = 0; l < 64; l++)
                c = fmaf(sl[l], g_features[((size_t)b * 64 + l) * 256 + tid], c);
            g_context[b * 256 + tid] = c;
        }
        grid_bar(nblk);

        // ---- Phase C: mx = context @ gru_k[:256]  (32x48 tiles, 4x32 grid) ----
        {
            float* As = sm;          // 16x32
            float* Bs = sm + 512;    // 16x48
            int bm = (bid >> 5) * 32;
            int bn = (bid & 31) * 48;
            int arow = tid >> 3, akc = (tid & 7) * 2;
            int tx = tid & 15, ty = tid >> 4;
            float acc[2][3] = {};
            for (int k0 = 0; k0 < 256; k0 += 16) {
                float2 av = *(const float2*)(g_context + (size_t)(bm + arow) * 256 + k0 + akc);
                As[(akc + 0) * 32 + arow] = av.x;
                As[(akc + 1) * 32 + arow] = av.y;
                if (tid < 192) {
                    int idx = tid * 4;
                    int kr = idx / 48, nc = idx % 48;
                    float4 bv = *(const float4*)(gru_k + (size_t)(k0 + kr) * 1536 + bn + nc);
                    *(float4*)&Bs[kr * 48 + nc] = bv;
                }
                __syncthreads();
                #pragma unroll
                for (int k = 0; k < 16; k++) {
                    float2 a = *(const float2*)&As[k * 32 + ty * 2];
                    float b0 = Bs[k * 48 + tx * 3 + 0];
                    float b1 = Bs[k * 48 + tx * 3 + 1];
                    float b2v = Bs[k * 48 + tx * 3 + 2];
                    acc[0][0] = fmaf(a.x, b0, acc[0][0]);
                    acc[0][1] = fmaf(a.x, b1, acc[0][1]);
                    acc[0][2] = fmaf(a.x, b2v, acc[0][2]);
                    acc[1][0] = fmaf(a.y, b0, acc[1][0]);
                    acc[1][1] = fmaf(a.y, b1, acc[1][1]);
                    acc[1][2] = fmaf(a.y, b2v, acc[1][2]);
                }
                __syncthreads();
            }
            int r0 = bm + ty * 2, c0 = bn + tx * 3;
            #pragma unroll
            for (int i = 0; i < 2; i++)
                #pragma unroll
                for (int j = 0; j < 3; j++)
                    g_mx[(size_t)(r0 + i) * 1536 + c0 + j] = acc[i][j];
        }
        grid_bar(nblk);

        // ---- Phase D: GRU pointwise (zero state => gru_rk dead) ----
        {
            int b = bid;
            size_t r = (size_t)t * 128 + b;
            #pragma unroll
            for (int i = 0; i < 2; i++) {
                int u = tid + i * 256;
                float xz = g_mx[b * 1536 + u]        + g_embmx[r * 1536 + u];
                float xr = g_mx[b * 1536 + 512 + u]  + g_embmx[r * 1536 + 512 + u];
                float xh = g_mx[b * 1536 + 1024 + u] + g_embmx[r * 1536 + 1024 + u];
                float rz = gru_b[1536 + u];
                float rr = gru_b[1536 + 512 + u];
                float rh = gru_b[1536 + 1024 + u];
                float z  = 1.f / (1.f + __expf(-(xz + rz)));
                float rg = 1.f / (1.f + __expf(-(xr + rr)));
                float hh = tanh_apx(xh + rg * rh);
                g_states[r * 512 + u] = (1.f - z) * hh;
            }
        }
        grid_bar(nblk);
    }
}

// ---------------- launch ----------------
extern "C" void kernel_launch(void* const* d_in, const int* in_sizes, int n_in,
                              void* d_out, int out_size)
{
    const float* img    = (const float*)d_in[0];
    const int*   target = (const int*)  d_in[1];
    const float* W_fc   = (const float*)d_in[2];
    const float* b_fc   = (const float*)d_in[3];
    const float* W1     = (const float*)d_in[4];
    const float* b1     = (const float*)d_in[5];
    const float* W2     = (const float*)d_in[6];
    const float* b2     = (const float*)d_in[7];
    const float* V      = (const float*)d_in[8];
    const float* bV     = (const float*)d_in[9];
    const float* emb    = (const float*)d_in[10];
    const float* gru_k  = (const float*)d_in[11];
    /* d_in[12] = gru_rk : dead (zero GRU state) */
    const float* gru_b  = (const float*)d_in[13];
    const float* fc1_w  = (const float*)d_in[14];
    const float* fc1_b  = (const float*)d_in[15];
    const float* fc2_w  = (const float*)d_in[16];
    const float* fc2_b  = (const float*)d_in[17];
    float* out = (float*)d_out;

    float *features, *featw1, *embtok, *embmx, *states, *fc1out;
    cudaGetSymbolAddress((void**)&features, g_features);
    cudaGetSymbolAddress((void**)&featw1,  g_featw1);
    cudaGetSymbolAddress((void**)&embtok,  g_embtok);
    cudaGetSymbolAddress((void**)&embmx,   g_embmx);
    cudaGetSymbolAddress((void**)&states,  g_states);
    cudaGetSymbolAddress((void**)&fc1out,  g_fc1out);

    // encoder: features = relu(img @ W_fc + b_fc)
    sgemm128_f2<<<dim3(2, 64), 256>>>(img, W_fc, b_fc, features, 8192, 256, 2048, 1, 0);
    // featw1 = features @ W1 + b1
    sgemm128_f2<<<dim3(4, 64), 256>>>(features, W1, b1, featw1, 8192, 512, 256, 0, 0);
    // token embeddings for all 47 steps
    gather_kernel<<<6016, 256>>>(target, emb);
    // embmx = embtok @ gru_k[256:,:] + gru_b[0]
    sgemm128_f2<<<dim3(12, 47), 256>>>(embtok, gru_k + 256 * 1536, gru_b, embmx, 6016, 1536, 256, 0, 0);

    // sequential 47-step loop: one persistent kernel with grid barriers
    step_loop_kernel<<<128, 256>>>(W2, V, bV, b2, gru_k, gru_b);

    // fc1out = states @ fc1_w + fc1_b
    sgemm128_f2<<<dim3(4, 47), 256>>>(states, fc1_w, fc1_b, fc1out, 6016, 512, 512, 0, 0);
    // out = fc1out @ fc2_w + fc2_b, remapped to (B, 47, VOCAB)
    sgemm128_f2<<<dim3(40, 47), 256>>>(fc1out, fc2_w, fc2_b, out, 6016, 5000, 512, 0, 1);
}

// round 4
// speedup vs baseline: 1.3418x; 1.3418x over previous
#include <cuda_runtime.h>
#include <cstdint>

#define TS 47

// ---------------- device scratch (allocation-free) ----------------
__device__ __align__(128) float g_features[8192 * 256];
__device__ __align__(128) float g_featw1 [8192 * 512];
__device__ __align__(128) float g_embtok [6016 * 256];
__device__ __align__(128) float g_embmx  [6016 * 1536];
__device__ __align__(128) float g_hidw2  [2 * 128 * 512];
__device__ __align__(128) float g_context[128 * 256];
__device__ __align__(128) float g_states [6016 * 512];
__device__ __align__(128) float g_fc1out [6016 * 512];

__device__ unsigned g_bar_cnt;
__device__ unsigned g_bar_gen;

// ---------------- helpers ----------------
__device__ __forceinline__ float tanh_apx(float x) {
    float y;
    asm("tanh.approx.f32 %0, %1;" : "=f"(y) : "f"(x));
    return y;
}

__device__ __forceinline__ unsigned ld_acq(const unsigned* p) {
    unsigned v;
    asm volatile("ld.acquire.gpu.global.u32 %0, [%1];" : "=r"(v) : "l"(p));
    return v;
}

__device__ __forceinline__ void grid_bar(int nblk) {
    __syncthreads();
    if (threadIdx.x == 0) {
        unsigned gen = ld_acq(&g_bar_gen);
        __threadfence();
        if (atomicAdd(&g_bar_cnt, 1u) == (unsigned)(nblk - 1)) {
            g_bar_cnt = 0;
            asm volatile("red.release.gpu.global.add.u32 [%0], 1;"
                         :: "l"(&g_bar_gen) : "memory");
        } else {
            while (ld_acq(&g_bar_gen) == gen) { }
        }
    }
    __syncthreads();
}

// ---------------- big GEMM: 128x128 tile, BK=8, 8x8 micro, DOUBLE-BUFFERED ----------------
// C[M,N] = act(A[M,K] @ B[K,N] + bias). M%128==0, K%8==0. N guarded.
// remap: A-row (t*128+b) stored to C-row (b*47+t).
__global__ __launch_bounds__(256, 2) void sgemm128_db(
    const float* __restrict__ A, const float* __restrict__ B,
    const float* __restrict__ bias, float* __restrict__ C,
    int M, int N, int K, int relu, int remap)
{
    __shared__ __align__(16) float As[2][8 * 128];
    __shared__ __align__(16) float Bs[2][8 * 128];

    int tid = threadIdx.x;
    int bm = blockIdx.y * 128;
    int bn = blockIdx.x * 128;
    int ar = tid >> 1;            // 0..127
    int ac = (tid & 1) * 4;       // 0 or 4
    int br = tid >> 5;            // 0..7
    int bc = (tid & 31) * 4;      // 0..124
    int tx = tid & 15, ty = tid >> 4;
    int gc = bn + bc;

    float acc[8][8] = {};
    const float* Ap = A + (size_t)(bm + ar) * K + ac;
    int niter = K >> 3;

    // prologue: load chunk 0
    float4 av = *(const float4*)(Ap);
    float4 bv;
    {
        const float* Bp = B + (size_t)br * N + gc;
        if (gc + 3 < N) bv = *(const float4*)Bp;
        else {
            bv.x = (gc + 0 < N) ? Bp[0] : 0.f;
            bv.y = (gc + 1 < N) ? Bp[1] : 0.f;
            bv.z = (gc + 2 < N) ? Bp[2] : 0.f;
            bv.w = (gc + 3 < N) ? Bp[3] : 0.f;
        }
    }
    As[0][(ac + 0) * 128 + ar] = av.x;
    As[0][(ac + 1) * 128 + ar] = av.y;
    As[0][(ac + 2) * 128 + ar] = av.z;
    As[0][(ac + 3) * 128 + ar] = av.w;
    *(float4*)&Bs[0][br * 128 + bc] = bv;
    __syncthreads();

    for (int i = 0; i < niter; i++) {
        int cur = i & 1;
        if (i + 1 < niter) {
            int k0 = (i + 1) * 8;
            av = *(const float4*)(Ap + k0);
            const float* Bp = B + (size_t)(k0 + br) * N + gc;
            if (gc + 3 < N) bv = *(const float4*)Bp;
            else {
                bv.x = (gc + 0 < N) ? Bp[0] : 0.f;
                bv.y = (gc + 1 < N) ? Bp[1] : 0.f;
                bv.z = (gc + 2 < N) ? Bp[2] : 0.f;
                bv.w = (gc + 3 < N) ? Bp[3] : 0.f;
            }
        }

        #pragma unroll
        for (int k = 0; k < 8; k++) {
            float a[8], b[8];
            float4 a0 = *(const float4*)&As[cur][k * 128 + ty * 4];
            float4 a1 = *(const float4*)&As[cur][k * 128 + 64 + ty * 4];
            float4 b0 = *(const float4*)&Bs[cur][k * 128 + tx * 4];
            float4 b1 = *(const float4*)&Bs[cur][k * 128 + 64 + tx * 4];
            a[0]=a0.x; a[1]=a0.y; a[2]=a0.z; a[3]=a0.w;
            a[4]=a1.x; a[5]=a1.y; a[6]=a1.z; a[7]=a1.w;
            b[0]=b0.x; b[1]=b0.y; b[2]=b0.z; b[3]=b0.w;
            b[4]=b1.x; b[5]=b1.y; b[6]=b1.z; b[7]=b1.w;
            #pragma unroll
            for (int ii = 0; ii < 8; ii++)
                #pragma unroll
                for (int jj = 0; jj < 8; jj++)
                    acc[ii][jj] = fmaf(a[ii], b[jj], acc[ii][jj]);
        }

        if (i + 1 < niter) {
            int nxt = cur ^ 1;
            As[nxt][(ac + 0) * 128 + ar] = av.x;
            As[nxt][(ac + 1) * 128 + ar] = av.y;
            As[nxt][(ac + 2) * 128 + ar] = av.z;
            As[nxt][(ac + 3) * 128 + ar] = av.w;
            *(float4*)&Bs[nxt][br * 128 + bc] = bv;
            __syncthreads();
        }
    }

    #pragma unroll
    for (int i = 0; i < 8; i++) {
        int grow = bm + ((i < 4) ? (ty * 4 + i) : (64 + ty * 4 + i - 4));
        size_t ro;
        if (remap) {
            int t = grow >> 7, b = grow & 127;
            ro = ((size_t)b * TS + t) * (size_t)N;
        } else {
            ro = (size_t)grow * (size_t)N;
        }
        #pragma unroll
        for (int j = 0; j < 8; j++) {
            int c = bn + ((j < 4) ? (tx * 4 + j) : (64 + tx * 4 + j - 4));
            if (c < N) {
                float v = acc[i][j] + (bias ? bias[c] : 0.f);
                if (relu) v = fmaxf(v, 0.f);
                C[ro + c] = v;
            }
        }
    }
}

// ---------------- token embedding gather ----------------
__global__ void gather_kernel(const int* __restrict__ target,
                              const float* __restrict__ emb)
{
    int row = blockIdx.x;
    int e = threadIdx.x;
    int t = row >> 7, b = row & 127;
    int tok = (t == 0) ? 1 : target[b * 48 + t];
    g_embtok[(size_t)row * 256 + e] = emb[(size_t)tok * 256 + e];
}

// ---------------- persistent step loop: 128 blocks, 47 timesteps, 3 bars/step ----------------
__global__ __launch_bounds__(256) void step_loop_kernel(
    const float* __restrict__ W2, const float* __restrict__ V,
    const float* __restrict__ bV, const float* __restrict__ b2,
    const float* __restrict__ gru_k, const float* __restrict__ gru_b)
{
    __shared__ float sm[4096 + 2 * 3072];   // 40KB
    const int bid = blockIdx.x;   // 0..127
    const int tid = threadIdx.x;  // 0..255
    const int nblk = 128;

    for (int t = 0; t < TS; t++) {
        // ---- Phase A: hidw2 = states[t-1] @ W2 (K-split 2, 32x32 tiles, staged) ----
        if (t > 0) {
            float* As = sm;              // [2][16*32]
            float* Bs = sm + 1024;       // [2][16*32]
            int z  = bid >> 6;
            int rr = bid & 63;
            int bm = (rr >> 4) * 32;
            int bn = (rr & 15) * 32;
            const float* A = g_states + (size_t)(t - 1) * 65536;
            float* C = g_hidw2 + z * 65536;
            int kbeg = z * 256;
            int arow = tid >> 3, akc = (tid & 7) * 2;
            int bkr = tid >> 4, bnc = (tid & 15) * 2;
            int tx = tid & 15, ty = tid >> 4;
            float a00 = 0.f, a01 = 0.f, a10 = 0.f, a11 = 0.f;

            float2 ra = *(const float2*)(A + (size_t)(bm + arow) * 512 + kbeg + akc);
            float2 rb = *(const float2*)(W2 + (size_t)(kbeg + bkr) * 512 + bn + bnc);
            As[akc * 32 + arow] = ra.x;
            As[(akc + 1) * 32 + arow] = ra.y;
            Bs[bkr * 32 + bnc] = rb.x;
            Bs[bkr * 32 + bnc + 1] = rb.y;
            __syncthreads();

            for (int c = 0; c < 16; c++) {
                int cur = c & 1;
                if (c + 1 < 16) {
                    int k0 = kbeg + (c + 1) * 16;
                    ra = *(const float2*)(A + (size_t)(bm + arow) * 512 + k0 + akc);
                    rb = *(const float2*)(W2 + (size_t)(k0 + bkr) * 512 + bn + bnc);
                }
                float* Ac = As + cur * 512;
                float* Bc = Bs + cur * 512;
                #pragma unroll
                for (int k = 0; k < 16; k++) {
                    float2 a = *(const float2*)&Ac[k * 32 + ty * 2];
                    float2 b = *(const float2*)&Bc[k * 32 + tx * 2];
                    a00 = fmaf(a.x, b.x, a00); a01 = fmaf(a.x, b.y, a01);
                    a10 = fmaf(a.y, b.x, a10); a11 = fmaf(a.y, b.y, a11);
                }
                if (c + 1 < 16) {
                    int nxt = cur ^ 1;
                    As[nxt * 512 + akc * 32 + arow] = ra.x;
                    As[nxt * 512 + (akc + 1) * 32 + arow] = ra.y;
                    Bs[nxt * 512 + bkr * 32 + bnc] = rb.x;
                    Bs[nxt * 512 + bkr * 32 + bnc + 1] = rb.y;
                    __syncthreads();
                }
            }
            int r0 = bm + ty * 2, c0 = bn + tx * 2;
            C[(size_t)(r0 + 0) * 512 + c0 + 0] = a00;
            C[(size_t)(r0 + 0) * 512 + c0 + 1] = a01;
            C[(size_t)(r0 + 1) * 512 + c0 + 0] = a10;
            C[(size_t)(r0 + 1) * 512 + c0 + 1] = a11;
            grid_bar(nblk);
        }

        // ---- Phase B: Bahdanau attention, block = batch element ----
        {
            float* hw2 = sm;
            float* sV  = sm + 512;
            float* sl  = sm + 1024;
            int b = bid;
            if (t > 0) {
                hw2[tid]       = g_hidw2[b * 512 + tid]       + g_hidw2[65536 + b * 512 + tid]       + b2[tid];
                hw2[tid + 256] = g_hidw2[b * 512 + tid + 256] + g_hidw2[65536 + b * 512 + tid + 256] + b2[tid + 256];
            } else {
                hw2[tid]       = b2[tid];
                hw2[tid + 256] = b2[tid + 256];
            }
            sV[tid]       = V[tid];
            sV[tid + 256] = V[tid + 256];
            __syncthreads();

            int w = tid >> 5, lane = tid & 31;
            #pragma unroll
            for (int p = 0; p < 8; p++) {
                int l = w * 8 + p;
                const float* row = g_featw1 + ((size_t)b * 64 + l) * 512;
                float a = 0.f;
                #pragma unroll
                for (int j = 0; j < 16; j++) {
                    int u = lane + j * 32;
                    float s = tanh_apx(row[u] + hw2[u]);
                    a = fmaf(s, sV[u], a);
                }
                #pragma unroll
                for (int o = 16; o; o >>= 1) a += __shfl_xor_sync(0xffffffffu, a, o);
                if (lane == 0) sl[l] = a + bV[0];
            }
            __syncthreads();

            if (tid < 32) {
                float v0 = sl[tid], v1 = sl[tid + 32];
                float m = fmaxf(v0, v1);
                #pragma unroll
                for (int o = 16; o; o >>= 1) m = fmaxf(m, __shfl_xor_sync(0xffffffffu, m, o));
                float e0 = __expf(v0 - m), e1 = __expf(v1 - m);
                float s = e0 + e1;
                #pragma unroll
                for (int o = 16; o; o >>= 1) s += __shfl_xor_sync(0xffffffffu, s, o);
                float inv = 1.0f / s;
                sl[tid] = e0 * inv;
                sl[tid + 32] = e1 * inv;
            }
            __syncthreads();

            float c = 0.f;
            #pragma unroll 8
            for (int l = 0; l < 64; l++)
                c = fmaf(sl[l], g_features[((size_t)b * 64 + l) * 256 + tid], c);
            g_context[b * 256 + tid] = c;
        }
        grid_bar(nblk);

        // ---- Phase C+D fused: mx = context @ gru_k[:256] + GRU pointwise -> states ----
        {
            float* sA = sm;              // 16 batches x 256 k  (4096)
            float* sB = sm + 4096;       // [2][3 gates][32 k][32 u]
            int u0 = (bid & 15) * 32;
            int b0 = (bid >> 4) * 16;
            int w = tid >> 5;            // 0..7 -> batch pair
            int lane = tid & 31;         // u within tile
            int row0 = 2 * w, row1 = row0 + 1;

            // load context tile (16x256) once
            for (int j = tid; j < 1024; j += 256) {
                int r = j >> 6, c4 = j & 63;
                *(float4*)&sA[r * 256 + c4 * 4] =
                    *(const float4*)(g_context + (size_t)(b0 + r) * 256 + c4 * 4);
            }
            // prologue: B chunk 0
            int bk = tid >> 3, bu4 = (tid & 7) * 4;
            float4 rb0 = *(const float4*)(gru_k + (size_t)bk * 1536 + u0 + bu4);
            float4 rb1 = *(const float4*)(gru_k + (size_t)bk * 1536 + 512 + u0 + bu4);
            float4 rb2 = *(const float4*)(gru_k + (size_t)bk * 1536 + 1024 + u0 + bu4);
            *(float4*)&sB[bk * 32 + bu4] = rb0;
            *(float4*)&sB[1024 + bk * 32 + bu4] = rb1;
            *(float4*)&sB[2048 + bk * 32 + bu4] = rb2;
            __syncthreads();

            float az0 = 0.f, ar0 = 0.f, ah0 = 0.f;
            float az1 = 0.f, ar1 = 0.f, ah1 = 0.f;

            for (int c = 0; c < 8; c++) {
                int cur = c & 1;
                if (c + 1 < 8) {
                    int k0 = (c + 1) * 32;
                    rb0 = *(const float4*)(gru_k + (size_t)(k0 + bk) * 1536 + u0 + bu4);
                    rb1 = *(const float4*)(gru_k + (size_t)(k0 + bk) * 1536 + 512 + u0 + bu4);
                    rb2 = *(const float4*)(gru_k + (size_t)(k0 + bk) * 1536 + 1024 + u0 + bu4);
                }
                const float* Bc = sB + cur * 3072;
                int kb = c * 32;
                #pragma unroll
                for (int k = 0; k < 32; k++) {
                    float bz = Bc[k * 32 + lane];
                    float br = Bc[1024 + k * 32 + lane];
                    float bh = Bc[2048 + k * 32 + lane];
                    float a0 = sA[row0 * 256 + kb + k];
                    float a1 = sA[row1 * 256 + kb + k];
                    az0 = fmaf(a0, bz, az0); ar0 = fmaf(a0, br, ar0); ah0 = fmaf(a0, bh, ah0);
                    az1 = fmaf(a1, bz, az1); ar1 = fmaf(a1, br, ar1); ah1 = fmaf(a1, bh, ah1);
                }
                if (c + 1 < 8) {
                    int nxt = cur ^ 1;
                    *(float4*)&sB[nxt * 3072 + bk * 32 + bu4] = rb0;
                    *(float4*)&sB[nxt * 3072 + 1024 + bk * 32 + bu4] = rb1;
                    *(float4*)&sB[nxt * 3072 + 2048 + bk * 32 + bu4] = rb2;
                    __syncthreads();
                }
            }

            // GRU pointwise + state write
            int u = u0 + lane;
            float rz = gru_b[1536 + u];
            float rr = gru_b[2048 + u];
            float rh = gru_b[2560 + u];
            #pragma unroll
            for (int i = 0; i < 2; i++) {
                int b = b0 + row0 + i;
                size_t r = (size_t)t * 128 + b;
                float xz = (i ? az1 : az0) + g_embmx[r * 1536 + u];
                float xr = (i ? ar1 : ar0) + g_embmx[r * 1536 + 512 + u];
                float xh = (i ? ah1 : ah0) + g_embmx[r * 1536 + 1024 + u];
                float z  = 1.f / (1.f + __expf(-(xz + rz)));
                float rg = 1.f / (1.f + __expf(-(xr + rr)));
                float hh = tanh_apx(xh + rg * rh);
                g_states[r * 512 + u] = (1.f - z) * hh;
            }
        }
        grid_bar(nblk);
    }
}

// ---------------- launch ----------------
extern "C" void kernel_launch(void* const* d_in, const int* in_sizes, int n_in,
                              void* d_out, int out_size)
{
    const float* img    = (const float*)d_in[0];
    const int*   target = (const int*)  d_in[1];
    const float* W_fc   = (const float*)d_in[2];
    const float* b_fc   = (const float*)d_in[3];
    const float* W1     = (const float*)d_in[4];
    const float* b1     = (const float*)d_in[5];
    const float* W2     = (const float*)d_in[6];
    const float* b2     = (const float*)d_in[7];
    const float* V      = (const float*)d_in[8];
    const float* bV     = (const float*)d_in[9];
    const float* emb    = (const float*)d_in[10];
    const float* gru_k  = (const float*)d_in[11];
    /* d_in[12] = gru_rk : dead (zero GRU state) */
    const float* gru_b  = (const float*)d_in[13];
    const float* fc1_w  = (const float*)d_in[14];
    const float* fc1_b  = (const float*)d_in[15];
    const float* fc2_w  = (const float*)d_in[16];
    const float* fc2_b  = (const float*)d_in[17];
    float* out = (float*)d_out;

    float *features, *featw1, *embtok, *embmx, *states, *fc1out;
    cudaGetSymbolAddress((void**)&features, g_features);
    cudaGetSymbolAddress((void**)&featw1,  g_featw1);
    cudaGetSymbolAddress((void**)&embtok,  g_embtok);
    cudaGetSymbolAddress((void**)&embmx,   g_embmx);
    cudaGetSymbolAddress((void**)&states,  g_states);
    cudaGetSymbolAddress((void**)&fc1out,  g_fc1out);

    sgemm128_db<<<dim3(2, 64), 256>>>(img, W_fc, b_fc, features, 8192, 256, 2048, 1, 0);
    sgemm128_db<<<dim3(4, 64), 256>>>(features, W1, b1, featw1, 8192, 512, 256, 0, 0);
    gather_kernel<<<6016, 256>>>(target, emb);
    sgemm128_db<<<dim3(12, 47), 256>>>(embtok, gru_k + 256 * 1536, gru_b, embmx, 6016, 1536, 256, 0, 0);

    step_loop_kernel<<<128, 256>>>(W2, V, bV, b2, gru_k, gru_b);

    sgemm128_db<<<dim3(4, 47), 256>>>(states, fc1_w, fc1_b, fc1out, 6016, 512, 512, 0, 0);
    sgemm128_db<<<dim3(40, 47), 256>>>(fc1out, fc2_w, fc2_b, out, 6016, 5000, 512, 0, 1);
}

// round 6
// speedup vs baseline: 1.7897x; 1.3338x over previous
#include <cuda_runtime.h>
#include <cuda_bf16.h>
#include <cstdint>

#define TS 47

// ---------------- device scratch (allocation-free) ----------------
__device__ __align__(128) float g_features[8192 * 256];
__device__ __align__(128) float g_featw1 [8192 * 512];
__device__ __align__(128) float g_embtok [6016 * 256];
__device__ __align__(128) float g_embmx  [6016 * 1536];
__device__ __align__(128) float g_hidw2  [2 * 128 * 512];
__device__ __align__(128) float g_context[128 * 256];
__device__ __align__(128) float g_states [6016 * 512];
__device__ __align__(128) float g_fc1out [6016 * 512];

__device__ unsigned g_bar_cnt;
__device__ unsigned g_bar_gen;

// ---------------- generic helpers ----------------
__device__ __forceinline__ float tanh_apx(float x) {
    float y;
    asm("tanh.approx.f32 %0, %1;" : "=f"(y) : "f"(x));
    return y;
}

__device__ __forceinline__ unsigned ld_acq(const unsigned* p) {
    unsigned v;
    asm volatile("ld.acquire.gpu.global.u32 %0, [%1];" : "=r"(v) : "l"(p));
    return v;
}

__device__ __forceinline__ void grid_bar(int nblk) {
    __syncthreads();
    if (threadIdx.x == 0) {
        unsigned gen = ld_acq(&g_bar_gen);
        __threadfence();
        if (atomicAdd(&g_bar_cnt, 1u) == (unsigned)(nblk - 1)) {
            g_bar_cnt = 0;
            asm volatile("red.release.gpu.global.add.u32 [%0], 1;"
                         :: "l"(&g_bar_gen) : "memory");
        } else {
            while (ld_acq(&g_bar_gen) == gen) { }
        }
    }
    __syncthreads();
}

// ---------------- mma.sync helpers (baseline PTX, no sm_103a features) ----------------
__device__ __forceinline__ uint32_t smem_u32(const void* p) {
    uint32_t a;
    asm("{ .reg .u64 t; cvta.to.shared.u64 t, %1; cvt.u32.u64 %0, t; }"
        : "=r"(a) : "l"(p));
    return a;
}

__device__ __forceinline__ void ldsm_x4(uint32_t* r, uint32_t addr) {
    asm volatile("ldmatrix.sync.aligned.m8n8.x4.shared.b16 {%0,%1,%2,%3}, [%4];"
        : "=r"(r[0]), "=r"(r[1]), "=r"(r[2]), "=r"(r[3]) : "r"(addr));
}

__device__ __forceinline__ void ldsm_x2t(uint32_t* r, uint32_t addr) {
    asm volatile("ldmatrix.sync.aligned.m8n8.x2.trans.shared.b16 {%0,%1}, [%2];"
        : "=r"(r[0]), "=r"(r[1]) : "r"(addr));
}

__device__ __forceinline__ void mma_bf16(float* c, const uint32_t* a, const uint32_t* b) {
    asm volatile("mma.sync.aligned.m16n8k16.row.col.f32.bf16.bf16.f32 "
        "{%0,%1,%2,%3},{%4,%5,%6,%7},{%8,%9},{%0,%1,%2,%3};"
        : "+f"(c[0]), "+f"(c[1]), "+f"(c[2]), "+f"(c[3])
        : "r"(a[0]), "r"(a[1]), "r"(a[2]), "r"(a[3]), "r"(b[0]), "r"(b[1]));
}

__device__ __forceinline__ uint32_t packbf(__nv_bfloat16 a, __nv_bfloat16 b) {
    __nv_bfloat162 t = __halves2bfloat162(a, b);
    return *(uint32_t*)&t;
}

// ---------------- bf16-split tensor-core GEMM ----------------
// C[M,N] = act(A@B + bias), fp32 in/out, 3-term bf16 split (err ~1.5e-5).
// 128x128 tile, BK=32, 8 warps (64x32 each). M%128==0, K%32==0, N guarded.
// remap: A-row (t*128+b) -> C-row (b*47+t).
#define ASTR 40     /* bf16 units per A smem row  (80B) */
#define BSTR 136    /* bf16 units per B smem row (272B) */
#define OFF_ALO 10240
#define OFF_BHI 20480
#define OFF_BLO 29184
#define STAGE   38912

__global__ void __launch_bounds__(256) mma_gemm(
    const float* __restrict__ A, const float* __restrict__ B,
    const float* __restrict__ bias, float* __restrict__ C,
    int M, int N, int K, int relu, int remap)
{
    extern __shared__ char smem[];
    const int tid = threadIdx.x;
    const int wid = tid >> 5, lane = tid & 31;
    const int bm = blockIdx.y * 128, bn = blockIdx.x * 128;
    const int wm = (wid >> 2) * 64;
    const int wn = (wid & 3) * 32;

    float acc[4][4][4] = {};
    const int nc = K >> 5;
    float4 va[4], vb[4];

    // ---- global load of chunk k0 into registers ----
    auto loadAB = [&](int k0) {
        #pragma unroll
        for (int i = 0; i < 4; i++) {
            int task = tid + (i << 8);
            int m = task >> 3, k4 = (task & 7) << 2;
            va[i] = *(const float4*)(A + (size_t)(bm + m) * K + k0 + k4);
        }
        #pragma unroll
        for (int i = 0; i < 4; i++) {
            int task = tid + (i << 8);
            int kk = task >> 5, n4 = (task & 31) << 2;
            int gc = bn + n4;
            const float* Bp = B + (size_t)(k0 + kk) * N + gc;
            if (gc + 3 < N) {
                vb[i] = *(const float4*)Bp;
            } else {
                vb[i].x = (gc + 0 < N) ? Bp[0] : 0.f;
                vb[i].y = (gc + 1 < N) ? Bp[1] : 0.f;
                vb[i].z = (gc + 2 < N) ? Bp[2] : 0.f;
                vb[i].w = (gc + 3 < N) ? Bp[3] : 0.f;
            }
        }
    };

    // ---- split fp32 -> (hi, lo) bf16 and store to smem stage ----
    auto cvtStore = [&](int stg) {
        char* sD = smem + stg * STAGE;
        __nv_bfloat16* Ahi = (__nv_bfloat16*)sD;
        __nv_bfloat16* Alo = (__nv_bfloat16*)(sD + OFF_ALO);
        __nv_bfloat16* Bhi = (__nv_bfloat16*)(sD + OFF_BHI);
        __nv_bfloat16* Blo = (__nv_bfloat16*)(sD + OFF_BLO);
        #pragma unroll
        for (int i = 0; i < 4; i++) {
            int task = tid + (i << 8);
            int m = task >> 3, k4 = (task & 7) << 2;
            __nv_bfloat16 hx = __float2bfloat16(va[i].x);
            __nv_bfloat16 hy = __float2bfloat16(va[i].y);
            __nv_bfloat16 hz = __float2bfloat16(va[i].z);
            __nv_bfloat16 hw = __float2bfloat16(va[i].w);
            __nv_bfloat16 lx = __float2bfloat16(va[i].x - __bfloat162float(hx));
            __nv_bfloat16 ly = __float2bfloat16(va[i].y - __bfloat162float(hy));
            __nv_bfloat16 lz = __float2bfloat16(va[i].z - __bfloat162float(hz));
            __nv_bfloat16 lw = __float2bfloat16(va[i].w - __bfloat162float(hw));
            *(uint2*)&Ahi[m * ASTR + k4] = make_uint2(packbf(hx, hy), packbf(hz, hw));
            *(uint2*)&Alo[m * ASTR + k4] = make_uint2(packbf(lx, ly), packbf(lz, lw));
        }
        #pragma unroll
        for (int i = 0; i < 4; i++) {
            int task = tid + (i << 8);
            int kk = task >> 5, n4 = (task & 31) << 2;
            __nv_bfloat16 hx = __float2bfloat16(vb[i].x);
            __nv_bfloat16 hy = __float2bfloat16(vb[i].y);
            __nv_bfloat16 hz = __float2bfloat16(vb[i].z);
            __nv_bfloat16 hw = __float2bfloat16(vb[i].w);
            __nv_bfloat16 lx = __float2bfloat16(vb[i].x - __bfloat162float(hx));
            __nv_bfloat16 ly = __float2bfloat16(vb[i].y - __bfloat162float(hy));
            __nv_bfloat16 lz = __float2bfloat16(vb[i].z - __bfloat162float(hz));
            __nv_bfloat16 lw = __float2bfloat16(vb[i].w - __bfloat162float(hw));
            *(uint2*)&Bhi[kk * BSTR + n4] = make_uint2(packbf(hx, hy), packbf(hz, hw));
            *(uint2*)&Blo[kk * BSTR + n4] = make_uint2(packbf(lx, ly), packbf(lz, lw));
        }
    };

    loadAB(0);
    cvtStore(0);
    __syncthreads();

    for (int c = 0; c < nc; c++) {
        int cur = c & 1;
        if (c + 1 < nc) loadAB((c + 1) << 5);

        uint32_t base = smem_u32(smem + cur * STAGE);
        uint32_t aAhi = base, aAlo = base + OFF_ALO;
        uint32_t aBhi = base + OFF_BHI, aBlo = base + OFF_BLO;

        #pragma unroll
        for (int kk = 0; kk < 2; kk++) {
            int kb = kk * 16;
            uint32_t ahi[4][4], alo[4][4];
            #pragma unroll
            for (int im = 0; im < 4; im++) {
                int row = wm + im * 16 + (lane & 15);
                uint32_t off = row * (ASTR * 2) + kb * 2 + ((lane >> 4) << 4);
                ldsm_x4(ahi[im], aAhi + off);
                ldsm_x4(alo[im], aAlo + off);
            }
            #pragma unroll
            for (int jn = 0; jn < 4; jn++) {
                int n = wn + jn * 8;
                uint32_t off = (kb + (lane & 15)) * (BSTR * 2) + n * 2;
                uint32_t bhi[2], blo[2];
                ldsm_x2t(bhi, aBhi + off);
                ldsm_x2t(blo, aBlo + off);
                #pragma unroll
                for (int im = 0; im < 4; im++) {
                    mma_bf16(acc[im][jn], ahi[im], bhi);
                    mma_bf16(acc[im][jn], alo[im], bhi);
                    mma_bf16(acc[im][jn], ahi[im], blo);
                }
            }
        }

        if (c + 1 < nc) cvtStore(cur ^ 1);
        __syncthreads();
    }

    // ---- epilogue: registers -> gmem with bias/relu/remap ----
    int tr = lane >> 2, tc = (lane & 3) << 1;
    #pragma unroll
    for (int im = 0; im < 4; im++) {
        #pragma unroll
        for (int half = 0; half < 2; half++) {
            int grow = bm + wm + im * 16 + tr + half * 8;
            size_t ro;
            if (remap) {
                int t = grow >> 7, b = grow & 127;
                ro = ((size_t)b * TS + t) * (size_t)N;
            } else {
                ro = (size_t)grow * (size_t)N;
            }
            #pragma unroll
            for (int jn = 0; jn < 4; jn++) {
                int gc = bn + wn + jn * 8 + tc;
                if (gc < N) {
                    float v0 = acc[im][jn][half * 2 + 0] + bias[gc];
                    float v1 = acc[im][jn][half * 2 + 1] + bias[gc + 1];
                    if (relu) { v0 = fmaxf(v0, 0.f); v1 = fmaxf(v1, 0.f); }
                    *(float2*)(C + ro + gc) = make_float2(v0, v1);
                }
            }
        }
    }
}

// ---------------- token embedding gather ----------------
__global__ void gather_kernel(const int* __restrict__ target,
                              const float* __restrict__ emb)
{
    int row = blockIdx.x;
    int e = threadIdx.x;
    int t = row >> 7, b = row & 127;
    int tok = (t == 0) ? 1 : target[b * 48 + t];
    g_embtok[(size_t)row * 256 + e] = emb[(size_t)tok * 256 + e];
}

// ---------------- persistent step loop: 128 blocks, 47 timesteps, 3 bars/step ----------------
__global__ __launch_bounds__(256) void step_loop_kernel(
    const float* __restrict__ W2, const float* __restrict__ V,
    const float* __restrict__ bV, const float* __restrict__ b2,
    const float* __restrict__ gru_k, const float* __restrict__ gru_b)
{
    __shared__ float sm[4096 + 2 * 3072];
    const int bid = blockIdx.x;
    const int tid = threadIdx.x;
    const int nblk = 128;

    for (int t = 0; t < TS; t++) {
        // ---- Phase A: hidw2 = states[t-1] @ W2 (K-split 2, 32x32 tiles, staged) ----
        if (t > 0) {
            float* As = sm;
            float* Bs = sm + 1024;
            int z  = bid >> 6;
            int rr = bid & 63;
            int bm = (rr >> 4) * 32;
            int bn = (rr & 15) * 32;
            const float* A = g_states + (size_t)(t - 1) * 65536;
            float* C = g_hidw2 + z * 65536;
            int kbeg = z * 256;
            int arow = tid >> 3, akc = (tid & 7) * 2;
            int bkr = tid >> 4, bnc = (tid & 15) * 2;
            int tx = tid & 15, ty = tid >> 4;
            float a00 = 0.f, a01 = 0.f, a10 = 0.f, a11 = 0.f;

            float2 ra = *(const float2*)(A + (size_t)(bm + arow) * 512 + kbeg + akc);
            float2 rb = *(const float2*)(W2 + (size_t)(kbeg + bkr) * 512 + bn + bnc);
            As[akc * 32 + arow] = ra.x;
            As[(akc + 1) * 32 + arow] = ra.y;
            Bs[bkr * 32 + bnc] = rb.x;
            Bs[bkr * 32 + bnc + 1] = rb.y;
            __syncthreads();

            for (int c = 0; c < 16; c++) {
                int cur = c & 1;
                if (c + 1 < 16) {
                    int k0 = kbeg + (c + 1) * 16;
                    ra = *(const float2*)(A + (size_t)(bm + arow) * 512 + k0 + akc);
                    rb = *(const float2*)(W2 + (size_t)(k0 + bkr) * 512 + bn + bnc);
                }
                float* Ac = As + cur * 512;
                float* Bc = Bs + cur * 512;
                #pragma unroll
                for (int k = 0; k < 16; k++) {
                    float2 a = *(const float2*)&Ac[k * 32 + ty * 2];
                    float2 b = *(const float2*)&Bc[k * 32 + tx * 2];
                    a00 = fmaf(a.x, b.x, a00); a01 = fmaf(a.x, b.y, a01);
                    a10 = fmaf(a.y, b.x, a10); a11 = fmaf(a.y, b.y, a11);
                }
                if (c + 1 < 16) {
                    int nxt = cur ^ 1;
                    As[nxt * 512 + akc * 32 + arow] = ra.x;
                    As[nxt * 512 + (akc + 1) * 32 + arow] = ra.y;
                    Bs[nxt * 512 + bkr * 32 + bnc] = rb.x;
                    Bs[nxt * 512 + bkr * 32 + bnc + 1] = rb.y;
                    __syncthreads();
                }
            }
            int r0 = bm + ty * 2, c0 = bn + tx * 2;
            C[(size_t)(r0 + 0) * 512 + c0 + 0] = a00;
            C[(size_t)(r0 + 0) * 512 + c0 + 1] = a01;
            C[(size_t)(r0 + 1) * 512 + c0 + 0] = a10;
            C[(size_t)(r0 + 1) * 512 + c0 + 1] = a11;
            grid_bar(nblk);
        }

        // ---- Phase B: Bahdanau attention ----
        {
            float* hw2 = sm;
            float* sV  = sm + 512;
            float* sl  = sm + 1024;
            int b = bid;
            if (t > 0) {
                hw2[tid]       = g_hidw2[b * 512 + tid]       + g_hidw2[65536 + b * 512 + tid]       + b2[tid];
                hw2[tid + 256] = g_hidw2[b * 512 + tid + 256] + g_hidw2[65536 + b * 512 + tid + 256] + b2[tid + 256];
            } else {
                hw2[tid]       = b2[tid];
                hw2[tid + 256] = b2[tid + 256];
            }
            sV[tid]       = V[tid];
            sV[tid + 256] = V[tid + 256];
            __syncthreads();

            int w = tid >> 5, lane = tid & 31;
            #pragma unroll
            for (int p = 0; p < 8; p++) {
                int l = w * 8 + p;
                const float* row = g_featw1 + ((size_t)b * 64 + l) * 512;
                float a = 0.f;
                #pragma unroll
                for (int j = 0; j < 16; j++) {
                    int u = lane + j * 32;
                    float s = tanh_apx(row[u] + hw2[u]);
                    a = fmaf(s, sV[u], a);
                }
                #pragma unroll
                for (int o = 16; o; o >>= 1) a += __shfl_xor_sync(0xffffffffu, a, o);
                if (lane == 0) sl[l] = a + bV[0];
            }
            __syncthreads();

            if (tid < 32) {
                float v0 = sl[tid], v1 = sl[tid + 32];
                float m = fmaxf(v0, v1);
                #pragma unroll
                for (int o = 16; o; o >>= 1) m = fmaxf(m, __shfl_xor_sync(0xffffffffu, m, o));
                float e0 = __expf(v0 - m), e1 = __expf(v1 - m);
                float s = e0 + e1;
                #pragma unroll
                for (int o = 16; o; o >>= 1) s += __shfl_xor_sync(0xffffffffu, s, o);
                float inv = 1.0f / s;
                sl[tid] = e0 * inv;
                sl[tid + 32] = e1 * inv;
            }
            __syncthreads();

            float c = 0.f;
            #pragma unroll 8
            for (int l = 0; l < 64; l++)
                c = fmaf(sl[l], g_features[((size_t)b * 64 + l) * 256 + tid], c);
            g_context[b * 256 + tid] = c;
        }
        grid_bar(nblk);

        // ---- Phase C+D fused: mx = context @ gru_k[:256] + GRU pointwise ----
        {
            float* sA = sm;
            float* sB = sm + 4096;
            int u0 = (bid & 15) * 32;
            int b0 = (bid >> 4) * 16;
            int w = tid >> 5;
            int lane = tid & 31;
            int row0 = 2 * w, row1 = row0 + 1;

            for (int j = tid; j < 1024; j += 256) {
                int r = j >> 6, c4 = j & 63;
                *(float4*)&sA[r * 256 + c4 * 4] =
                    *(const float4*)(g_context + (size_t)(b0 + r) * 256 + c4 * 4);
            }
            int bk = tid >> 3, bu4 = (tid & 7) * 4;
            float4 rb0 = *(const float4*)(gru_k + (size_t)bk * 1536 + u0 + bu4);
            float4 rb1 = *(const float4*)(gru_k + (size_t)bk * 1536 + 512 + u0 + bu4);
            float4 rb2 = *(const float4*)(gru_k + (size_t)bk * 1536 + 1024 + u0 + bu4);
            *(float4*)&sB[bk * 32 + bu4] = rb0;
            *(float4*)&sB[1024 + bk * 32 + bu4] = rb1;
            *(float4*)&sB[2048 + bk * 32 + bu4] = rb2;
            __syncthreads();

            float az0 = 0.f, ar0 = 0.f, ah0 = 0.f;
            float az1 = 0.f, ar1 = 0.f, ah1 = 0.f;

            for (int c = 0; c < 8; c++) {
                int cur = c & 1;
                if (c + 1 < 8) {
                    int k0 = (c + 1) * 32;
                    rb0 = *(const float4*)(gru_k + (size_t)(k0 + bk) * 1536 + u0 + bu4);
                    rb1 = *(const float4*)(gru_k + (size_t)(k0 + bk) * 1536 + 512 + u0 + bu4);
                    rb2 = *(const float4*)(gru_k + (size_t)(k0 + bk) * 1536 + 1024 + u0 + bu4);
                }
                const float* Bc = sB + cur * 3072;
                int kb = c * 32;
                #pragma unroll
                for (int k = 0; k < 32; k++) {
                    float bz = Bc[k * 32 + lane];
                    float br = Bc[1024 + k * 32 + lane];
                    float bh = Bc[2048 + k * 32 + lane];
                    float a0 = sA[row0 * 256 + kb + k];
                    float a1 = sA[row1 * 256 + kb + k];
                    az0 = fmaf(a0, bz, az0); ar0 = fmaf(a0, br, ar0); ah0 = fmaf(a0, bh, ah0);
                    az1 = fmaf(a1, bz, az1); ar1 = fmaf(a1, br, ar1); ah1 = fmaf(a1, bh, ah1);
                }
                if (c + 1 < 8) {
                    int nxt = cur ^ 1;
                    *(float4*)&sB[nxt * 3072 + bk * 32 + bu4] = rb0;
                    *(float4*)&sB[nxt * 3072 + 1024 + bk * 32 + bu4] = rb1;
                    *(float4*)&sB[nxt * 3072 + 2048 + bk * 32 + bu4] = rb2;
                    __syncthreads();
                }
            }

            int u = u0 + lane;
            float rz = gru_b[1536 + u];
            float rr = gru_b[2048 + u];
            float rh = gru_b[2560 + u];
            #pragma unroll
            for (int i = 0; i < 2; i++) {
                int b = b0 + row0 + i;
                size_t r = (size_t)t * 128 + b;
                float xz = (i ? az1 : az0) + g_embmx[r * 1536 + u];
                float xr = (i ? ar1 : ar0) + g_embmx[r * 1536 + 512 + u];
                float xh = (i ? ah1 : ah0) + g_embmx[r * 1536 + 1024 + u];
                float z  = 1.f / (1.f + __expf(-(xz + rz)));
                float rg = 1.f / (1.f + __expf(-(xr + rr)));
                float hh = tanh_apx(xh + rg * rh);
                g_states[r * 512 + u] = (1.f - z) * hh;
            }
        }
        grid_bar(nblk);
    }
}

// ---------------- launch ----------------
extern "C" void kernel_launch(void* const* d_in, const int* in_sizes, int n_in,
                              void* d_out, int out_size)
{
    const float* img    = (const float*)d_in[0];
    const int*   target = (const int*)  d_in[1];
    const float* W_fc   = (const float*)d_in[2];
    const float* b_fc   = (const float*)d_in[3];
    const float* W1     = (const float*)d_in[4];
    const float* b1     = (const float*)d_in[5];
    const float* W2     = (const float*)d_in[6];
    const float* b2     = (const float*)d_in[7];
    const float* V      = (const float*)d_in[8];
    const float* bV     = (const float*)d_in[9];
    const float* emb    = (const float*)d_in[10];
    const float* gru_k  = (const float*)d_in[11];
    /* d_in[12] = gru_rk : dead (zero GRU state) */
    const float* gru_b  = (const float*)d_in[13];
    const float* fc1_w  = (const float*)d_in[14];
    const float* fc1_b  = (const float*)d_in[15];
    const float* fc2_w  = (const float*)d_in[16];
    const float* fc2_b  = (const float*)d_in[17];
    float* out = (float*)d_out;

    float *features, *featw1, *embtok, *embmx, *states, *fc1out;
    cudaGetSymbolAddress((void**)&features, g_features);
    cudaGetSymbolAddress((void**)&featw1,  g_featw1);
    cudaGetSymbolAddress((void**)&embtok,  g_embtok);
    cudaGetSymbolAddress((void**)&embmx,   g_embmx);
    cudaGetSymbolAddress((void**)&states,  g_states);
    cudaGetSymbolAddress((void**)&fc1out,  g_fc1out);

    const int SMEM_SZ = 2 * STAGE;   // 77824 B
    cudaFuncSetAttribute(mma_gemm, cudaFuncAttributeMaxDynamicSharedMemorySize, SMEM_SZ);

    mma_gemm<<<dim3(2, 64), 256, SMEM_SZ>>>(img, W_fc, b_fc, features, 8192, 256, 2048, 1, 0);
    mma_gemm<<<dim3(4, 64), 256, SMEM_SZ>>>(features, W1, b1, featw1, 8192, 512, 256, 0, 0);
    gather_kernel<<<6016, 256>>>(target, emb);
    mma_gemm<<<dim3(12, 47), 256, SMEM_SZ>>>(embtok, gru_k + 256 * 1536, gru_b, embmx, 6016, 1536, 256, 0, 0);

    step_loop_kernel<<<128, 256>>>(W2, V, bV, b2, gru_k, gru_b);

    mma_gemm<<<dim3(4, 47), 256, SMEM_SZ>>>(states, fc1_w, fc1_b, fc1out, 6016, 512, 512, 0, 0);
    mma_gemm<<<dim3(40, 47), 256, SMEM_SZ>>>(fc1out, fc2_w, fc2_b, out, 6016, 5000, 512, 0, 1);
}